// round 13
// baseline (speedup 1.0000x reference)
#include <cuda_runtime.h>
#include <cuda_bf16.h>
#include <math.h>
#include <stdint.h>

#define BATCH 4096
#define KDIM  2048
#define NDIM  2048
#define DEPTH 16

// ---------------- device scratch (no allocation allowed) ----------------
__device__ __nv_bfloat16 g_Ahi[(size_t)BATCH * KDIM];
__device__ __nv_bfloat16 g_Alo[(size_t)BATCH * KDIM];
__device__ __nv_bfloat16 g_Bhi[(size_t)KDIM * NDIM];
__device__ __nv_bfloat16 g_Blo[(size_t)KDIM * NDIM];
__device__ float g_padd[NDIM];   // bias + probs, fused

// ---------------- fused prep: A-split | B-split | probs ----------------
#define A4BLKS 8192              // BATCH*KDIM/4/256
#define B4BLKS 4096              // KDIM*NDIM/4/256
#define PRBLKS 8                 // NDIM/256
__device__ __forceinline__ void split4(const float* __restrict__ src,
                                       __nv_bfloat16* __restrict__ hi,
                                       __nv_bfloat16* __restrict__ lo, int i) {
    float4 v = ((const float4*)src)[i];
    __nv_bfloat16 h0 = __float2bfloat16_rn(v.x), h1 = __float2bfloat16_rn(v.y);
    __nv_bfloat16 h2 = __float2bfloat16_rn(v.z), h3 = __float2bfloat16_rn(v.w);
    __nv_bfloat16 l0 = __float2bfloat16_rn(v.x - __bfloat162float(h0));
    __nv_bfloat16 l1 = __float2bfloat16_rn(v.y - __bfloat162float(h1));
    __nv_bfloat16 l2 = __float2bfloat16_rn(v.z - __bfloat162float(h2));
    __nv_bfloat16 l3 = __float2bfloat16_rn(v.w - __bfloat162float(h3));
    __nv_bfloat162* hp = (__nv_bfloat162*)(hi + 4 * (size_t)i);
    __nv_bfloat162* lp = (__nv_bfloat162*)(lo + 4 * (size_t)i);
    hp[0] = __nv_bfloat162(h0, h1); hp[1] = __nv_bfloat162(h2, h3);
    lp[0] = __nv_bfloat162(l0, l1); lp[1] = __nv_bfloat162(l2, l3);
}

__global__ void prep_kernel(const float* __restrict__ x,
                            const float* __restrict__ cw,
                            const float* __restrict__ aw,
                            const float* __restrict__ cb,
                            __nv_bfloat16* __restrict__ ahi,
                            __nv_bfloat16* __restrict__ alo,
                            __nv_bfloat16* __restrict__ bhi,
                            __nv_bfloat16* __restrict__ blo) {
    const int b = blockIdx.x, t = threadIdx.x;
    if (b < A4BLKS) {
        split4(x, ahi, alo, b * 256 + t);
    } else if (b < A4BLKS + B4BLKS) {
        split4(cw, bhi, blo, (b - A4BLKS) * 256 + t);
    } else {
        // probs[j] = (prod cos W[d,j,g])^2 / DIN  (uniform state kills sin terms)
        const int j = (b - A4BLKS - B4BLKS) * 256 + t;
        float p = 1.0f;
#pragma unroll
        for (int d = 0; d < DEPTH; ++d) {
            const float* base = aw + ((size_t)d * KDIM + j) * NDIM;
            p *= cosf(base[0]);
            p *= cosf(base[1]);
            p *= cosf(base[2]);
        }
        g_padd[j] = cb[j] + (p * p) * (1.0f / (float)KDIM);
    }
}

// ---------------- tensor-core GEMM + tanh ----------------
// out = tanh( Ahi*Bhi + Ahi*Blo + Alo*Bhi + padd )
#define BM 128
#define BN 128
#define BK 64
#define NK (KDIM / BK)       // 32
#define NSTAGE 3
#define NT 256

// padded smem rows: 16B-chunk strides 9 (A) and 17 (B) -> conflict-free ldmatrix
#define ROWA_B 144                           // 64 bf16 = 128B data + 16 pad
#define ROWB_B 272                           // 128 bf16 = 256B data + 16 pad
#define AHI_OFF 0
#define ALO_OFF (128 * ROWA_B)               // 18432
#define BHI_OFF (2 * 128 * ROWA_B)           // 36864
#define BLO_OFF (BHI_OFF + 64 * ROWB_B)      // 54272
#define STAGE_B (BHI_OFF + 2 * 64 * ROWB_B)  // 71680
#define SMEM_TOTAL (NSTAGE * STAGE_B)        // 215040

__device__ __forceinline__ void cp16(uint32_t dst, const void* src) {
    asm volatile("cp.async.cg.shared.global [%0], [%1], 16;\n" ::"r"(dst), "l"(src));
}
#define LDSM4(R, ADDR)                                                           \
    asm volatile("ldmatrix.sync.aligned.m8n8.x4.shared.b16 {%0,%1,%2,%3}, [%4];" \
                 : "=r"(R[0]), "=r"(R[1]), "=r"(R[2]), "=r"(R[3]) : "r"(ADDR))
#define LDSM4T(R, ADDR)                                                                \
    asm volatile("ldmatrix.sync.aligned.m8n8.x4.trans.shared.b16 {%0,%1,%2,%3}, [%4];" \
                 : "=r"(R[0]), "=r"(R[1]), "=r"(R[2]), "=r"(R[3]) : "r"(ADDR))
#define MMA(C, A, B0, B1)                                               \
    asm volatile("mma.sync.aligned.m16n8k16.row.col.f32.bf16.bf16.f32 " \
                 "{%0,%1,%2,%3},{%4,%5,%6,%7},{%8,%9},{%0,%1,%2,%3};"   \
                 : "+f"(C[0]), "+f"(C[1]), "+f"(C[2]), "+f"(C[3])       \
                 : "r"(A[0]), "r"(A[1]), "r"(A[2]), "r"(A[3]), "r"(B0), "r"(B1))

// prefetch all fragments for (stage base ST, k16 index K16) into buffer NB
#define PREFETCH(NB, ST, K16)                                                  \
    do {                                                                       \
        _Pragma("unroll") for (int mi = 0; mi < 4; ++mi) {                     \
            const uint32_t ad = (ST) + a_base + mi * 16 * ROWA_B + (K16) * 32; \
            LDSM4(ah[NB][mi], ad + AHI_OFF);                                   \
            LDSM4(al[NB][mi], ad + ALO_OFF);                                   \
        }                                                                      \
        _Pragma("unroll") for (int n16 = 0; n16 < 2; ++n16) {                  \
            const uint32_t bd =                                                \
                (ST) + b_base + (K16) * 16 * ROWB_B + n16 * 32;                \
            LDSM4T(bh[NB][n16], bd + BHI_OFF);                                 \
            LDSM4T(bl[NB][n16], bd + BLO_OFF);                                 \
        }                                                                      \
    } while (0)

__global__ __launch_bounds__(NT, 1) void gemm_tanh_kernel(float* __restrict__ out) {
    extern __shared__ char smem[];
    const uint32_t sbase = (uint32_t)__cvta_generic_to_shared(smem);

    const int tid  = threadIdx.x;
    const int lane = tid & 31;
    const int wid  = tid >> 5;
    const int wm = (wid & 1) * 64;    // 2 warps over M (64-row tiles)
    const int wn = (wid >> 1) * 32;   // 4 warps over N (32-col tiles)
    const int bm = blockIdx.y * BM;
    const int bn = blockIdx.x * BN;

    const __nv_bfloat16* Ah = g_Ahi + (size_t)bm * KDIM;
    const __nv_bfloat16* Al = g_Alo + (size_t)bm * KDIM;
    const __nv_bfloat16* Bh = g_Bhi + bn;
    const __nv_bfloat16* Bl = g_Blo + bn;

    float acc[4][4][4];   // [mi][n8][frag]
#pragma unroll
    for (int i = 0; i < 4; ++i)
#pragma unroll
        for (int j = 0; j < 4; ++j)
#pragma unroll
            for (int k = 0; k < 4; ++k) acc[i][j][k] = 0.0f;

    // double-buffered fragments
    uint32_t ah[2][4][4], al[2][4][4], bh[2][2][4], bl[2][2][4];

    const int r16 = lane & 15, h4 = lane >> 4;
    const uint32_t a_base = (uint32_t)((wm + r16) * ROWA_B + h4 * 16);
    const uint32_t b_base = (uint32_t)(r16 * ROWB_B + (wn + 8 * h4) * 2);

    auto load_stage = [&](int s, int kt) {
        const uint32_t st = sbase + s * STAGE_B;
        const int k0 = kt * BK;
        // A hi/lo: 128 rows x 8 chunks of 16B (1024 chunks, 4/thread each)
#pragma unroll
        for (int i = 0; i < 4; ++i) {
            const int f = tid + i * NT;
            const int r = f >> 3, c = f & 7;
            const uint32_t so = (uint32_t)(r * ROWA_B + c * 16);
            const size_t go = (size_t)r * KDIM + k0 + c * 8;
            cp16(st + AHI_OFF + so, Ah + go);
            cp16(st + ALO_OFF + so, Al + go);
        }
        // B hi/lo: 64 rows x 16 chunks of 16B (1024 chunks, 4/thread each)
#pragma unroll
        for (int i = 0; i < 4; ++i) {
            const int f = tid + i * NT;
            const int r = f >> 4, c = f & 15;
            const uint32_t so = (uint32_t)(r * ROWB_B + c * 16);
            const size_t go = (size_t)(k0 + r) * NDIM + c * 8;
            cp16(st + BHI_OFF + so, Bh + go);
            cp16(st + BLO_OFF + so, Bl + go);
        }
    };

    // prologue: fill stages 0 and 1, publish, prefetch first fragments
    load_stage(0, 0);
    asm volatile("cp.async.commit_group;\n");
    load_stage(1, 1);
    asm volatile("cp.async.commit_group;\n");
    asm volatile("cp.async.wait_group 0;\n");
    __syncthreads();
    PREFETCH(0, sbase, 0);

    int s_cur = 0;
    for (int kt = 0; kt < NK; ++kt) {
        const uint32_t st = sbase + s_cur * STAGE_B;
        int s_nxt = s_cur + 1; if (s_nxt == NSTAGE) s_nxt = 0;
        const uint32_t stn = sbase + s_nxt * STAGE_B;

        // kick the load for stage kt+2 (stage being overwritten was fully
        // consumed before the barrier below of the PREVIOUS iteration)
        if (kt + 2 < NK) {
            int s_ld = s_nxt + 1; if (s_ld == NSTAGE) s_ld = 0;
            load_stage(s_ld, kt + 2);
            asm volatile("cp.async.commit_group;\n");
        }

#pragma unroll
        for (int k16 = 0; k16 < BK / 16; ++k16) {
            const int cb = k16 & 1, nb = cb ^ 1;
            // prefetch next fragments (within stage, or k16=0 of next stage)
            if (k16 < BK / 16 - 1) {
                PREFETCH(nb, st, k16 + 1);
            } else if (kt + 1 < NK) {
                PREFETCH(nb, stn, 0);
            }
            // ---- 48 MMAs on current buffer, pass-major ----
#pragma unroll
            for (int n16 = 0; n16 < 2; ++n16)
#pragma unroll
                for (int mi = 0; mi < 4; ++mi) {
                    MMA(acc[mi][2 * n16 + 0], ah[cb][mi], bh[cb][n16][0], bh[cb][n16][1]);
                    MMA(acc[mi][2 * n16 + 1], ah[cb][mi], bh[cb][n16][2], bh[cb][n16][3]);
                }
#pragma unroll
            for (int n16 = 0; n16 < 2; ++n16)
#pragma unroll
                for (int mi = 0; mi < 4; ++mi) {
                    MMA(acc[mi][2 * n16 + 0], ah[cb][mi], bl[cb][n16][0], bl[cb][n16][1]);
                    MMA(acc[mi][2 * n16 + 1], ah[cb][mi], bl[cb][n16][2], bl[cb][n16][3]);
                }
#pragma unroll
            for (int n16 = 0; n16 < 2; ++n16)
#pragma unroll
                for (int mi = 0; mi < 4; ++mi) {
                    MMA(acc[mi][2 * n16 + 0], al[cb][mi], bh[cb][n16][0], bh[cb][n16][1]);
                    MMA(acc[mi][2 * n16 + 1], al[cb][mi], bh[cb][n16][2], bh[cb][n16][3]);
                }
        }

        // publish stage kt+2 for everyone; stage kt+1 already resident
        if (kt + 1 < NK) {
            asm volatile("cp.async.wait_group 0;\n");
            __syncthreads();
        }
        s_cur = s_nxt;
    }

    // ---------------- epilogue: + (bias+probs), tanh ----------------
    const int g = lane >> 2, tig = lane & 3;
    float2 badd[4];
#pragma unroll
    for (int ni = 0; ni < 4; ++ni)
        badd[ni] = *(const float2*)(g_padd + bn + wn + ni * 8 + 2 * tig);
#pragma unroll
    for (int mi = 0; mi < 4; ++mi) {
        const int row0 = bm + wm + mi * 16 + g;
#pragma unroll
        for (int ni = 0; ni < 4; ++ni) {
            const int col = bn + wn + ni * 8 + 2 * tig;
            float2 v0, v1;
            v0.x = tanhf(acc[mi][ni][0] + badd[ni].x);
            v0.y = tanhf(acc[mi][ni][1] + badd[ni].y);
            v1.x = tanhf(acc[mi][ni][2] + badd[ni].x);
            v1.y = tanhf(acc[mi][ni][3] + badd[ni].y);
            *(float2*)(out + (size_t)row0 * NDIM + col) = v0;
            *(float2*)(out + (size_t)(row0 + 8) * NDIM + col) = v1;
        }
    }
}

// ---------------- launch ----------------
extern "C" void kernel_launch(void* const* d_in, const int* in_sizes, int n_in,
                              void* d_out, int out_size) {
    (void)in_sizes; (void)n_in; (void)out_size;
    const float* x  = (const float*)d_in[0];
    const float* aw = (const float*)d_in[1];
    const float* cw = (const float*)d_in[2];
    const float* cb = (const float*)d_in[3];
    float* out = (float*)d_out;

    static bool attr_done = false;
    if (!attr_done) {
        cudaFuncSetAttribute(gemm_tanh_kernel,
                             cudaFuncAttributeMaxDynamicSharedMemorySize, SMEM_TOTAL);
        attr_done = true;
    }

    __nv_bfloat16 *ahi, *alo, *bhi, *blo;
    cudaGetSymbolAddress((void**)&ahi, g_Ahi);
    cudaGetSymbolAddress((void**)&alo, g_Alo);
    cudaGetSymbolAddress((void**)&bhi, g_Bhi);
    cudaGetSymbolAddress((void**)&blo, g_Blo);

    prep_kernel<<<A4BLKS + B4BLKS + PRBLKS, 256>>>(x, cw, aw, cb, ahi, alo, bhi, blo);

    dim3 grid(NDIM / BN, BATCH / BM);
    gemm_tanh_kernel<<<grid, NT, SMEM_TOTAL>>>(out);
}

// round 14
// speedup vs baseline: 1.0006x; 1.0006x over previous
#include <cuda_runtime.h>
#include <cuda_bf16.h>
#include <math.h>
#include <stdint.h>

#define BATCH 4096
#define KDIM  2048
#define NDIM  2048
#define DEPTH 16

// ---------------- device scratch (no allocation allowed) ----------------
__device__ __nv_bfloat16 g_Ahi[(size_t)BATCH * KDIM];
__device__ __nv_bfloat16 g_Alo[(size_t)BATCH * KDIM];
__device__ __nv_bfloat16 g_Bhi[(size_t)KDIM * NDIM];
__device__ __nv_bfloat16 g_Blo[(size_t)KDIM * NDIM];
__device__ float g_padd[NDIM];   // bias + probs, fused

// ---------------- fused prep: A-split | B-split | probs ----------------
#define A4BLKS 8192              // BATCH*KDIM/4/256
#define B4BLKS 4096              // KDIM*NDIM/4/256
#define PRBLKS 8                 // NDIM/256
__device__ __forceinline__ void split4(const float* __restrict__ src,
                                       __nv_bfloat16* __restrict__ hi,
                                       __nv_bfloat16* __restrict__ lo, int i) {
    float4 v = ((const float4*)src)[i];
    __nv_bfloat16 h0 = __float2bfloat16_rn(v.x), h1 = __float2bfloat16_rn(v.y);
    __nv_bfloat16 h2 = __float2bfloat16_rn(v.z), h3 = __float2bfloat16_rn(v.w);
    __nv_bfloat16 l0 = __float2bfloat16_rn(v.x - __bfloat162float(h0));
    __nv_bfloat16 l1 = __float2bfloat16_rn(v.y - __bfloat162float(h1));
    __nv_bfloat16 l2 = __float2bfloat16_rn(v.z - __bfloat162float(h2));
    __nv_bfloat16 l3 = __float2bfloat16_rn(v.w - __bfloat162float(h3));
    __nv_bfloat162* hp = (__nv_bfloat162*)(hi + 4 * (size_t)i);
    __nv_bfloat162* lp = (__nv_bfloat162*)(lo + 4 * (size_t)i);
    hp[0] = __nv_bfloat162(h0, h1); hp[1] = __nv_bfloat162(h2, h3);
    lp[0] = __nv_bfloat162(l0, l1); lp[1] = __nv_bfloat162(l2, l3);
}

__global__ void prep_kernel(const float* __restrict__ x,
                            const float* __restrict__ cw,
                            const float* __restrict__ aw,
                            const float* __restrict__ cb,
                            __nv_bfloat16* __restrict__ ahi,
                            __nv_bfloat16* __restrict__ alo,
                            __nv_bfloat16* __restrict__ bhi,
                            __nv_bfloat16* __restrict__ blo) {
    const int b = blockIdx.x, t = threadIdx.x;
    if (b < A4BLKS) {
        split4(x, ahi, alo, b * 256 + t);
    } else if (b < A4BLKS + B4BLKS) {
        split4(cw, bhi, blo, (b - A4BLKS) * 256 + t);
    } else {
        // probs[j] = (prod cos W[d,j,g])^2 / DIN  (uniform state kills sin terms)
        const int j = (b - A4BLKS - B4BLKS) * 256 + t;
        float p = 1.0f;
#pragma unroll
        for (int d = 0; d < DEPTH; ++d) {
            const float* base = aw + ((size_t)d * KDIM + j) * NDIM;
            p *= cosf(base[0]);
            p *= cosf(base[1]);
            p *= cosf(base[2]);
        }
        g_padd[j] = cb[j] + (p * p) * (1.0f / (float)KDIM);
    }
}

// ---------------- tensor-core GEMM + tanh ----------------
// out = tanh( Ahi*Bhi + Ahi*Blo + Alo*Bhi + padd )
#define BM 128
#define BN 128
#define BK 64
#define NK (KDIM / BK)       // 32
#define NSTAGE 3
#define NT 256

// padded smem rows: 16B-chunk strides 9 (A) and 17 (B) -> conflict-free ldmatrix
#define ROWA_B 144                           // 64 bf16 = 128B data + 16 pad
#define ROWB_B 272                           // 128 bf16 = 256B data + 16 pad
#define AHI_OFF 0
#define ALO_OFF (128 * ROWA_B)               // 18432
#define BHI_OFF (2 * 128 * ROWA_B)           // 36864
#define BLO_OFF (BHI_OFF + 64 * ROWB_B)      // 54272
#define STAGE_B (BHI_OFF + 2 * 64 * ROWB_B)  // 71680
#define SMEM_TOTAL (NSTAGE * STAGE_B)        // 215040

__device__ __forceinline__ void cp16(uint32_t dst, const void* src) {
    asm volatile("cp.async.cg.shared.global [%0], [%1], 16;\n" ::"r"(dst), "l"(src));
}
#define LDSM4(R, ADDR)                                                           \
    asm volatile("ldmatrix.sync.aligned.m8n8.x4.shared.b16 {%0,%1,%2,%3}, [%4];" \
                 : "=r"(R[0]), "=r"(R[1]), "=r"(R[2]), "=r"(R[3]) : "r"(ADDR))
#define LDSM4T(R, ADDR)                                                                \
    asm volatile("ldmatrix.sync.aligned.m8n8.x4.trans.shared.b16 {%0,%1,%2,%3}, [%4];" \
                 : "=r"(R[0]), "=r"(R[1]), "=r"(R[2]), "=r"(R[3]) : "r"(ADDR))
#define MMA(C, A, B0, B1)                                               \
    asm volatile("mma.sync.aligned.m16n8k16.row.col.f32.bf16.bf16.f32 " \
                 "{%0,%1,%2,%3},{%4,%5,%6,%7},{%8,%9},{%0,%1,%2,%3};"   \
                 : "+f"(C[0]), "+f"(C[1]), "+f"(C[2]), "+f"(C[3])       \
                 : "r"(A[0]), "r"(A[1]), "r"(A[2]), "r"(A[3]), "r"(B0), "r"(B1))

// prefetch all fragments for (stage base ST, k16 index K16) into buffer NB
#define PREFETCH(NB, ST, K16)                                                  \
    do {                                                                       \
        _Pragma("unroll") for (int mi = 0; mi < 4; ++mi) {                     \
            const uint32_t ad = (ST) + a_base + mi * 16 * ROWA_B + (K16) * 32; \
            LDSM4(ah[NB][mi], ad + AHI_OFF);                                   \
            LDSM4(al[NB][mi], ad + ALO_OFF);                                   \
        }                                                                      \
        _Pragma("unroll") for (int n16 = 0; n16 < 2; ++n16) {                  \
            const uint32_t bd =                                                \
                (ST) + b_base + (K16) * 16 * ROWB_B + n16 * 32;                \
            LDSM4T(bh[NB][n16], bd + BHI_OFF);                                 \
            LDSM4T(bl[NB][n16], bd + BLO_OFF);                                 \
        }                                                                      \
    } while (0)

__global__ __launch_bounds__(NT, 1) void gemm_tanh_kernel(float* __restrict__ out) {
    extern __shared__ char smem[];
    const uint32_t sbase = (uint32_t)__cvta_generic_to_shared(smem);

    const int tid  = threadIdx.x;
    const int lane = tid & 31;
    const int wid  = tid >> 5;
    const int wm = (wid & 1) * 64;    // 2 warps over M (64-row tiles)
    const int wn = (wid >> 1) * 32;   // 4 warps over N (32-col tiles)
    const int bm = blockIdx.y * BM;
    const int bn = blockIdx.x * BN;

    const __nv_bfloat16* Ah = g_Ahi + (size_t)bm * KDIM;
    const __nv_bfloat16* Al = g_Alo + (size_t)bm * KDIM;
    const __nv_bfloat16* Bh = g_Bhi + bn;
    const __nv_bfloat16* Bl = g_Blo + bn;

    float acc[4][4][4];   // [mi][n8][frag]
#pragma unroll
    for (int i = 0; i < 4; ++i)
#pragma unroll
        for (int j = 0; j < 4; ++j)
#pragma unroll
            for (int k = 0; k < 4; ++k) acc[i][j][k] = 0.0f;

    // double-buffered fragments
    uint32_t ah[2][4][4], al[2][4][4], bh[2][2][4], bl[2][2][4];

    const int r16 = lane & 15, h4 = lane >> 4;
    const uint32_t a_base = (uint32_t)((wm + r16) * ROWA_B + h4 * 16);
    const uint32_t b_base = (uint32_t)(r16 * ROWB_B + (wn + 8 * h4) * 2);

    auto load_stage = [&](int s, int kt) {
        const uint32_t st = sbase + s * STAGE_B;
        const int k0 = kt * BK;
        // A hi/lo: 128 rows x 8 chunks of 16B (1024 chunks, 4/thread each)
#pragma unroll
        for (int i = 0; i < 4; ++i) {
            const int f = tid + i * NT;
            const int r = f >> 3, c = f & 7;
            const uint32_t so = (uint32_t)(r * ROWA_B + c * 16);
            const size_t go = (size_t)r * KDIM + k0 + c * 8;
            cp16(st + AHI_OFF + so, Ah + go);
            cp16(st + ALO_OFF + so, Al + go);
        }
        // B hi/lo: 64 rows x 16 chunks of 16B (1024 chunks, 4/thread each)
#pragma unroll
        for (int i = 0; i < 4; ++i) {
            const int f = tid + i * NT;
            const int r = f >> 4, c = f & 15;
            const uint32_t so = (uint32_t)(r * ROWB_B + c * 16);
            const size_t go = (size_t)(k0 + r) * NDIM + c * 8;
            cp16(st + BHI_OFF + so, Bh + go);
            cp16(st + BLO_OFF + so, Bl + go);
        }
    };

    // prologue: fill stages 0 and 1, publish, prefetch first fragments
    load_stage(0, 0);
    asm volatile("cp.async.commit_group;\n");
    load_stage(1, 1);
    asm volatile("cp.async.commit_group;\n");
    asm volatile("cp.async.wait_group 0;\n");
    __syncthreads();
    PREFETCH(0, sbase, 0);

    int s_cur = 0;
    for (int kt = 0; kt < NK; ++kt) {
        const uint32_t st = sbase + s_cur * STAGE_B;
        int s_nxt = s_cur + 1; if (s_nxt == NSTAGE) s_nxt = 0;
        const uint32_t stn = sbase + s_nxt * STAGE_B;

        // kick the load for stage kt+2 (stage being overwritten was fully
        // consumed before the barrier below of the PREVIOUS iteration)
        if (kt + 2 < NK) {
            int s_ld = s_nxt + 1; if (s_ld == NSTAGE) s_ld = 0;
            load_stage(s_ld, kt + 2);
            asm volatile("cp.async.commit_group;\n");
        }

#pragma unroll
        for (int k16 = 0; k16 < BK / 16; ++k16) {
            const int cb = k16 & 1, nb = cb ^ 1;
            // prefetch next fragments (within stage, or k16=0 of next stage)
            if (k16 < BK / 16 - 1) {
                PREFETCH(nb, st, k16 + 1);
            } else if (kt + 1 < NK) {
                PREFETCH(nb, stn, 0);
            }
            // ---- 48 MMAs on current buffer, pass-major ----
#pragma unroll
            for (int n16 = 0; n16 < 2; ++n16)
#pragma unroll
                for (int mi = 0; mi < 4; ++mi) {
                    MMA(acc[mi][2 * n16 + 0], ah[cb][mi], bh[cb][n16][0], bh[cb][n16][1]);
                    MMA(acc[mi][2 * n16 + 1], ah[cb][mi], bh[cb][n16][2], bh[cb][n16][3]);
                }
#pragma unroll
            for (int n16 = 0; n16 < 2; ++n16)
#pragma unroll
                for (int mi = 0; mi < 4; ++mi) {
                    MMA(acc[mi][2 * n16 + 0], ah[cb][mi], bl[cb][n16][0], bl[cb][n16][1]);
                    MMA(acc[mi][2 * n16 + 1], ah[cb][mi], bl[cb][n16][2], bl[cb][n16][3]);
                }
#pragma unroll
            for (int n16 = 0; n16 < 2; ++n16)
#pragma unroll
                for (int mi = 0; mi < 4; ++mi) {
                    MMA(acc[mi][2 * n16 + 0], al[cb][mi], bh[cb][n16][0], bh[cb][n16][1]);
                    MMA(acc[mi][2 * n16 + 1], al[cb][mi], bh[cb][n16][2], bh[cb][n16][3]);
                }
        }

        // publish stage kt+2 for everyone; stage kt+1 already resident
        if (kt + 1 < NK) {
            asm volatile("cp.async.wait_group 0;\n");
            __syncthreads();
        }
        s_cur = s_nxt;
    }

    // ---------------- epilogue: + (bias+probs), tanh ----------------
    const int g = lane >> 2, tig = lane & 3;
    float2 badd[4];
#pragma unroll
    for (int ni = 0; ni < 4; ++ni)
        badd[ni] = *(const float2*)(g_padd + bn + wn + ni * 8 + 2 * tig);
#pragma unroll
    for (int mi = 0; mi < 4; ++mi) {
        const int row0 = bm + wm + mi * 16 + g;
#pragma unroll
        for (int ni = 0; ni < 4; ++ni) {
            const int col = bn + wn + ni * 8 + 2 * tig;
            float2 v0, v1;
            v0.x = tanhf(acc[mi][ni][0] + badd[ni].x);
            v0.y = tanhf(acc[mi][ni][1] + badd[ni].y);
            v1.x = tanhf(acc[mi][ni][2] + badd[ni].x);
            v1.y = tanhf(acc[mi][ni][3] + badd[ni].y);
            *(float2*)(out + (size_t)row0 * NDIM + col) = v0;
            *(float2*)(out + (size_t)(row0 + 8) * NDIM + col) = v1;
        }
    }
}

// ---------------- launch ----------------
extern "C" void kernel_launch(void* const* d_in, const int* in_sizes, int n_in,
                              void* d_out, int out_size) {
    (void)in_sizes; (void)n_in; (void)out_size;
    const float* x  = (const float*)d_in[0];
    const float* aw = (const float*)d_in[1];
    const float* cw = (const float*)d_in[2];
    const float* cb = (const float*)d_in[3];
    float* out = (float*)d_out;

    static bool attr_done = false;
    if (!attr_done) {
        cudaFuncSetAttribute(gemm_tanh_kernel,
                             cudaFuncAttributeMaxDynamicSharedMemorySize, SMEM_TOTAL);
        attr_done = true;
    }

    __nv_bfloat16 *ahi, *alo, *bhi, *blo;
    cudaGetSymbolAddress((void**)&ahi, g_Ahi);
    cudaGetSymbolAddress((void**)&alo, g_Alo);
    cudaGetSymbolAddress((void**)&bhi, g_Bhi);
    cudaGetSymbolAddress((void**)&blo, g_Blo);

    prep_kernel<<<A4BLKS + B4BLKS + PRBLKS, 256>>>(x, cw, aw, cb, ahi, alo, bhi, blo);

    dim3 grid(NDIM / BN, BATCH / BM);
    gemm_tanh_kernel<<<grid, NT, SMEM_TOTAL>>>(out);
}

// round 15
// speedup vs baseline: 1.0533x; 1.0527x over previous
#include <cuda_runtime.h>
#include <cuda_bf16.h>
#include <math.h>
#include <stdint.h>

#define BATCH 4096
#define KDIM  2048
#define NDIM  2048
#define DEPTH 16

// ---------------- device scratch (no allocation allowed) ----------------
__device__ __nv_bfloat16 g_Ahi[(size_t)BATCH * KDIM];
__device__ __nv_bfloat16 g_Alo[(size_t)BATCH * KDIM];
__device__ __nv_bfloat16 g_Bhi[(size_t)KDIM * NDIM];
__device__ __nv_bfloat16 g_Blo[(size_t)KDIM * NDIM];
__device__ float g_padd[NDIM];   // bias + probs, fused

// ---------------- fused prep: A-split | B-split | probs (ILP=4) ----------------
// Each thread processes 4 float4s (stride 256 float4s) -> MLP>=4 hides DRAM latency.
#define A16BLKS 2048             // BATCH*KDIM / (16 floats/thread) / 256
#define B16BLKS 1024             // KDIM*NDIM  / 16 / 256
#define PRBLKS  8                // NDIM/256

__device__ __forceinline__ void split1(float v, __nv_bfloat16& h, __nv_bfloat16& l) {
    h = __float2bfloat16_rn(v);
    l = __float2bfloat16_rn(v - __bfloat162float(h));
}

__device__ __forceinline__ void split16(const float* __restrict__ src,
                                        __nv_bfloat16* __restrict__ hi,
                                        __nv_bfloat16* __restrict__ lo,
                                        int blk, int t) {
    const int base = blk * 1024 + t;     // in float4 units
    float4 v[4];
#pragma unroll
    for (int k = 0; k < 4; ++k) v[k] = ((const float4*)src)[base + k * 256];
#pragma unroll
    for (int k = 0; k < 4; ++k) {
        __nv_bfloat16 h0, h1, h2, h3, l0, l1, l2, l3;
        split1(v[k].x, h0, l0);
        split1(v[k].y, h1, l1);
        split1(v[k].z, h2, l2);
        split1(v[k].w, h3, l3);
        const size_t o = 4 * (size_t)(base + k * 256);
        __nv_bfloat162* hp = (__nv_bfloat162*)(hi + o);
        __nv_bfloat162* lp = (__nv_bfloat162*)(lo + o);
        hp[0] = __nv_bfloat162(h0, h1);
        hp[1] = __nv_bfloat162(h2, h3);
        lp[0] = __nv_bfloat162(l0, l1);
        lp[1] = __nv_bfloat162(l2, l3);
    }
}

__global__ void prep_kernel(const float* __restrict__ x,
                            const float* __restrict__ cw,
                            const float* __restrict__ aw,
                            const float* __restrict__ cb,
                            __nv_bfloat16* __restrict__ ahi,
                            __nv_bfloat16* __restrict__ alo,
                            __nv_bfloat16* __restrict__ bhi,
                            __nv_bfloat16* __restrict__ blo) {
    const int b = blockIdx.x, t = threadIdx.x;
    if (b < A16BLKS) {
        split16(x, ahi, alo, b, t);
    } else if (b < A16BLKS + B16BLKS) {
        split16(cw, bhi, blo, b - A16BLKS, t);
    } else {
        // probs[j] = (prod cos W[d,j,g])^2 / DIN  (uniform state kills sin terms)
        const int j = (b - A16BLKS - B16BLKS) * 256 + t;
        float p = 1.0f;
#pragma unroll
        for (int d = 0; d < DEPTH; ++d) {
            const float* base = aw + ((size_t)d * KDIM + j) * NDIM;
            p *= cosf(base[0]);
            p *= cosf(base[1]);
            p *= cosf(base[2]);
        }
        g_padd[j] = cb[j] + (p * p) * (1.0f / (float)KDIM);
    }
}

// ---------------- tensor-core GEMM + tanh (R6 configuration, best measured) ----------------
// out = tanh( Ahi*Bhi + Ahi*Blo + Alo*Bhi + padd )
#define BM 128
#define BN 256
#define BK 64
#define NK (KDIM / BK)       // 32
#define NSTAGE 2

// padded smem rows: 16B-chunk strides 9 (A) and 33 (B) -> conflict-free ldmatrix
#define ROWA_B 144                           // 64 bf16 = 128B data, pad to 144B
#define ROWB_B 528                           // 256 bf16 = 512B data, pad to 528B
#define AHI_OFF 0
#define ALO_OFF (128 * ROWA_B)               // 18432
#define BHI_OFF (2 * 128 * ROWA_B)           // 36864
#define BLO_OFF (BHI_OFF + 64 * ROWB_B)      // 70656
#define STAGE_B (BHI_OFF + 2 * 64 * ROWB_B)  // 104448
#define SMEM_TOTAL (NSTAGE * STAGE_B)        // 208896

__device__ __forceinline__ void cp16(uint32_t dst, const void* src) {
    asm volatile("cp.async.cg.shared.global [%0], [%1], 16;\n" ::"r"(dst), "l"(src));
}
#define LDSM4(R, ADDR)                                                           \
    asm volatile("ldmatrix.sync.aligned.m8n8.x4.shared.b16 {%0,%1,%2,%3}, [%4];" \
                 : "=r"(R[0]), "=r"(R[1]), "=r"(R[2]), "=r"(R[3]) : "r"(ADDR))
#define LDSM4T(R, ADDR)                                                                \
    asm volatile("ldmatrix.sync.aligned.m8n8.x4.trans.shared.b16 {%0,%1,%2,%3}, [%4];" \
                 : "=r"(R[0]), "=r"(R[1]), "=r"(R[2]), "=r"(R[3]) : "r"(ADDR))
#define MMA(C, A, B0, B1)                                               \
    asm volatile("mma.sync.aligned.m16n8k16.row.col.f32.bf16.bf16.f32 " \
                 "{%0,%1,%2,%3},{%4,%5,%6,%7},{%8,%9},{%0,%1,%2,%3};"   \
                 : "+f"(C[0]), "+f"(C[1]), "+f"(C[2]), "+f"(C[3])       \
                 : "r"(A[0]), "r"(A[1]), "r"(A[2]), "r"(A[3]), "r"(B0), "r"(B1))

__global__ __launch_bounds__(256, 1) void gemm_tanh_kernel(float* __restrict__ out) {
    extern __shared__ char smem[];
    const uint32_t sbase = (uint32_t)__cvta_generic_to_shared(smem);

    const int tid  = threadIdx.x;
    const int lane = tid & 31;
    const int wid  = tid >> 5;
    const int wm = (wid & 1) * 64;    // 2 warps over M
    const int wn = (wid >> 1) * 64;   // 4 warps over N
    const int bm = blockIdx.y * BM;
    const int bn = blockIdx.x * BN;

    const __nv_bfloat16* Ah = g_Ahi + (size_t)bm * KDIM;
    const __nv_bfloat16* Al = g_Alo + (size_t)bm * KDIM;
    const __nv_bfloat16* Bh = g_Bhi + bn;
    const __nv_bfloat16* Bl = g_Blo + bn;

    float acc[4][8][4];
#pragma unroll
    for (int i = 0; i < 4; ++i)
#pragma unroll
        for (int j = 0; j < 8; ++j)
#pragma unroll
            for (int k = 0; k < 4; ++k) acc[i][j][k] = 0.0f;

    // ldmatrix base addresses (byte offsets within a stage)
    const int r16 = lane & 15, h4 = lane >> 4;
    const uint32_t a_base = (uint32_t)((wm + r16) * ROWA_B + h4 * 16);
    const uint32_t b_base = (uint32_t)(r16 * ROWB_B + (wn + 8 * h4) * 2);

    auto load_stage = [&](int s, int kt) {
        const uint32_t st = sbase + s * STAGE_B;
        const int k0 = kt * BK;
        // A hi/lo: 128 rows x 8 chunks of 16B (1024 chunks, 4 per thread)
#pragma unroll
        for (int i = 0; i < 4; ++i) {
            const int f = tid + i * 256;
            const int r = f >> 3, c = f & 7;
            const uint32_t so = (uint32_t)(r * ROWA_B + c * 16);
            const size_t go = (size_t)r * KDIM + k0 + c * 8;
            cp16(st + AHI_OFF + so, Ah + go);
            cp16(st + ALO_OFF + so, Al + go);
        }
        // B hi/lo: 64 rows x 32 chunks of 16B (2048 chunks, 8 per thread)
#pragma unroll
        for (int i = 0; i < 8; ++i) {
            const int f = tid + i * 256;
            const int r = f >> 5, c = f & 31;
            const uint32_t so = (uint32_t)(r * ROWB_B + c * 16);
            const size_t go = (size_t)(k0 + r) * NDIM + c * 8;
            cp16(st + BHI_OFF + so, Bh + go);
            cp16(st + BLO_OFF + so, Bl + go);
        }
    };

    load_stage(0, 0);
    asm volatile("cp.async.commit_group;\n");

    for (int kt = 0; kt < NK; ++kt) {
        const int s = kt & 1;
        asm volatile("cp.async.wait_group 0;\n");
        __syncthreads();

        if (kt + 1 < NK) {
            load_stage(s ^ 1, kt + 1);
            asm volatile("cp.async.commit_group;\n");
        }

        const uint32_t st = sbase + s * STAGE_B;
#pragma unroll
        for (int k16 = 0; k16 < BK / 16; ++k16) {
            // ---- front-load ALL fragments for this k16 (16 LDSM.x4) ----
            uint32_t ah[4][4], al[4][4], bh[4][4], bl[4][4];
#pragma unroll
            for (int mi = 0; mi < 4; ++mi) {
                const uint32_t ad = st + a_base + mi * 16 * ROWA_B + k16 * 32;
                LDSM4(ah[mi], ad + AHI_OFF);
                LDSM4(al[mi], ad + ALO_OFF);
            }
#pragma unroll
            for (int n16 = 0; n16 < 4; ++n16) {
                const uint32_t bd = st + b_base + k16 * 16 * ROWB_B + n16 * 32;
                LDSM4T(bh[n16], bd + BHI_OFF);
                LDSM4T(bl[n16], bd + BLO_OFF);
            }
            // ---- 96 uninterrupted MMAs, pass-major ----
#pragma unroll
            for (int n16 = 0; n16 < 4; ++n16)
#pragma unroll
                for (int mi = 0; mi < 4; ++mi) {
                    MMA(acc[mi][2 * n16 + 0], ah[mi], bh[n16][0], bh[n16][1]);
                    MMA(acc[mi][2 * n16 + 1], ah[mi], bh[n16][2], bh[n16][3]);
                }
#pragma unroll
            for (int n16 = 0; n16 < 4; ++n16)
#pragma unroll
                for (int mi = 0; mi < 4; ++mi) {
                    MMA(acc[mi][2 * n16 + 0], ah[mi], bl[n16][0], bl[n16][1]);
                    MMA(acc[mi][2 * n16 + 1], ah[mi], bl[n16][2], bl[n16][3]);
                }
#pragma unroll
            for (int n16 = 0; n16 < 4; ++n16)
#pragma unroll
                for (int mi = 0; mi < 4; ++mi) {
                    MMA(acc[mi][2 * n16 + 0], al[mi], bh[n16][0], bh[n16][1]);
                    MMA(acc[mi][2 * n16 + 1], al[mi], bh[n16][2], bh[n16][3]);
                }
        }
    }

    // ---------------- epilogue: + (bias+probs), tanh ----------------
    const int g = lane >> 2, tig = lane & 3;
    float2 badd[8];
#pragma unroll
    for (int ni = 0; ni < 8; ++ni)
        badd[ni] = *(const float2*)(g_padd + bn + wn + ni * 8 + 2 * tig);
#pragma unroll
    for (int mi = 0; mi < 4; ++mi) {
        const int row0 = bm + wm + mi * 16 + g;
#pragma unroll
        for (int ni = 0; ni < 8; ++ni) {
            const int col = bn + wn + ni * 8 + 2 * tig;
            float2 v0, v1;
            v0.x = tanhf(acc[mi][ni][0] + badd[ni].x);
            v0.y = tanhf(acc[mi][ni][1] + badd[ni].y);
            v1.x = tanhf(acc[mi][ni][2] + badd[ni].x);
            v1.y = tanhf(acc[mi][ni][3] + badd[ni].y);
            *(float2*)(out + (size_t)row0 * NDIM + col) = v0;
            *(float2*)(out + (size_t)(row0 + 8) * NDIM + col) = v1;
        }
    }
}

// ---------------- launch ----------------
extern "C" void kernel_launch(void* const* d_in, const int* in_sizes, int n_in,
                              void* d_out, int out_size) {
    (void)in_sizes; (void)n_in; (void)out_size;
    const float* x  = (const float*)d_in[0];
    const float* aw = (const float*)d_in[1];
    const float* cw = (const float*)d_in[2];
    const float* cb = (const float*)d_in[3];
    float* out = (float*)d_out;

    static bool attr_done = false;
    if (!attr_done) {
        cudaFuncSetAttribute(gemm_tanh_kernel,
                             cudaFuncAttributeMaxDynamicSharedMemorySize, SMEM_TOTAL);
        attr_done = true;
    }

    __nv_bfloat16 *ahi, *alo, *bhi, *blo;
    cudaGetSymbolAddress((void**)&ahi, g_Ahi);
    cudaGetSymbolAddress((void**)&alo, g_Alo);
    cudaGetSymbolAddress((void**)&bhi, g_Bhi);
    cudaGetSymbolAddress((void**)&blo, g_Blo);

    prep_kernel<<<A16BLKS + B16BLKS + PRBLKS, 256>>>(x, cw, aw, cb, ahi, alo, bhi, blo);

    dim3 grid(NDIM / BN, BATCH / BM);
    gemm_tanh_kernel<<<grid, 256, SMEM_TOTAL>>>(out);
}

// round 16
// speedup vs baseline: 1.0813x; 1.0266x over previous
#include <cuda_runtime.h>
#include <cuda_bf16.h>
#include <math.h>
#include <stdint.h>

#define BATCH 4096
#define KDIM  2048
#define NDIM  2048
#define DEPTH 16

// ---------------- device scratch (no allocation allowed) ----------------
__device__ __nv_bfloat16 g_Ahi[(size_t)BATCH * KDIM];
__device__ __nv_bfloat16 g_Alo[(size_t)BATCH * KDIM];
__device__ __nv_bfloat16 g_Bhi[(size_t)KDIM * NDIM];
__device__ __nv_bfloat16 g_Blo[(size_t)KDIM * NDIM];
__device__ float g_padd[NDIM];   // bias + probs, fused

// ---------------- fused prep: A-split | B-split | probs ----------------
// 16 floats/thread, 16B-aligned packed stores, 4 independent 16B loads (MLP=4).
#define ABLKS 2048               // BATCH*KDIM / (16 floats/thread * 256 thr)
#define BBLKS 1024               // KDIM*NDIM  / 4096
#define PRBLKS 8                 // NDIM/256

__device__ __forceinline__ uint32_t pack2(__nv_bfloat16 a, __nv_bfloat16 b) {
    __nv_bfloat162 t(a, b);
    return *(uint32_t*)&t;
}
__device__ __forceinline__ void split1(float v, __nv_bfloat16& h, __nv_bfloat16& l) {
    h = __float2bfloat16_rn(v);
    l = __float2bfloat16_rn(v - __bfloat162float(h));
}

// block blk handles float4 indices [blk*1024, (blk+1)*1024) of src
__device__ __forceinline__ void splitblk(const float* __restrict__ src,
                                         __nv_bfloat16* __restrict__ hi,
                                         __nv_bfloat16* __restrict__ lo,
                                         int blk, int t) {
    const float4* src4 = (const float4*)src;
    uint4* hi4 = (uint4*)hi;
    uint4* lo4 = (uint4*)lo;
#pragma unroll
    for (int i = 0; i < 2; ++i) {
        const int f = blk * 1024 + i * 512 + 2 * t;   // even
        float4 v0 = src4[f];
        float4 v1 = src4[f + 1];
        __nv_bfloat16 h0, h1, h2, h3, h4, h5, h6, h7;
        __nv_bfloat16 l0, l1, l2, l3, l4, l5, l6, l7;
        split1(v0.x, h0, l0); split1(v0.y, h1, l1);
        split1(v0.z, h2, l2); split1(v0.w, h3, l3);
        split1(v1.x, h4, l4); split1(v1.y, h5, l5);
        split1(v1.z, h6, l6); split1(v1.w, h7, l7);
        uint4 H = make_uint4(pack2(h0, h1), pack2(h2, h3), pack2(h4, h5), pack2(h6, h7));
        uint4 L = make_uint4(pack2(l0, l1), pack2(l2, l3), pack2(l4, l5), pack2(l6, l7));
        hi4[f >> 1] = H;
        lo4[f >> 1] = L;
    }
}

__global__ void prep_kernel(const float* __restrict__ x,
                            const float* __restrict__ cw,
                            const float* __restrict__ aw,
                            const float* __restrict__ cb,
                            __nv_bfloat16* __restrict__ ahi,
                            __nv_bfloat16* __restrict__ alo,
                            __nv_bfloat16* __restrict__ bhi,
                            __nv_bfloat16* __restrict__ blo) {
    const int b = blockIdx.x, t = threadIdx.x;
    if (b < ABLKS) {
        splitblk(x, ahi, alo, b, t);
    } else if (b < ABLKS + BBLKS) {
        splitblk(cw, bhi, blo, b - ABLKS, t);
    } else {
        // probs[j] = (prod cos W[d,j,g])^2 / DIN  (uniform state kills sin terms)
        const int j = (b - ABLKS - BBLKS) * 256 + t;
        float p = 1.0f;
#pragma unroll
        for (int d = 0; d < DEPTH; ++d) {
            const float* base = aw + ((size_t)d * KDIM + j) * NDIM;
            p *= cosf(base[0]);
            p *= cosf(base[1]);
            p *= cosf(base[2]);
        }
        g_padd[j] = cb[j] + (p * p) * (1.0f / (float)KDIM);
    }
}

// ---------------- tensor-core GEMM + tanh (R7 configuration, best measured) ----------------
// out = tanh( Ahi*Bhi + Ahi*Blo + Alo*Bhi + padd )
#define BM 128
#define BN 256
#define BK 64
#define NK (KDIM / BK)       // 32
#define NSTAGE 2
#define NTHREADS 512

// padded smem rows: 16B-chunk strides 9 (A) and 33 (B) -> conflict-free ldmatrix
#define ROWA_B 144                           // 64 bf16 = 128B data, pad to 144B
#define ROWB_B 528                           // 256 bf16 = 512B data, pad to 528B
#define AHI_OFF 0
#define ALO_OFF (128 * ROWA_B)               // 18432
#define BHI_OFF (2 * 128 * ROWA_B)           // 36864
#define BLO_OFF (BHI_OFF + 64 * ROWB_B)      // 70656
#define STAGE_B (BHI_OFF + 2 * 64 * ROWB_B)  // 104448
#define SMEM_TOTAL (NSTAGE * STAGE_B)        // 208896

__device__ __forceinline__ void cp16(uint32_t dst, const void* src) {
    asm volatile("cp.async.cg.shared.global [%0], [%1], 16;\n" ::"r"(dst), "l"(src));
}
#define LDSM4(R, ADDR)                                                           \
    asm volatile("ldmatrix.sync.aligned.m8n8.x4.shared.b16 {%0,%1,%2,%3}, [%4];" \
                 : "=r"(R[0]), "=r"(R[1]), "=r"(R[2]), "=r"(R[3]) : "r"(ADDR))
#define LDSM4T(R, ADDR)                                                                \
    asm volatile("ldmatrix.sync.aligned.m8n8.x4.trans.shared.b16 {%0,%1,%2,%3}, [%4];" \
                 : "=r"(R[0]), "=r"(R[1]), "=r"(R[2]), "=r"(R[3]) : "r"(ADDR))
#define MMA(C, A, B0, B1)                                               \
    asm volatile("mma.sync.aligned.m16n8k16.row.col.f32.bf16.bf16.f32 " \
                 "{%0,%1,%2,%3},{%4,%5,%6,%7},{%8,%9},{%0,%1,%2,%3};"   \
                 : "+f"(C[0]), "+f"(C[1]), "+f"(C[2]), "+f"(C[3])       \
                 : "r"(A[0]), "r"(A[1]), "r"(A[2]), "r"(A[3]), "r"(B0), "r"(B1))

__global__ __launch_bounds__(NTHREADS, 1) void gemm_tanh_kernel(float* __restrict__ out) {
    extern __shared__ char smem[];
    const uint32_t sbase = (uint32_t)__cvta_generic_to_shared(smem);

    const int tid  = threadIdx.x;
    const int lane = tid & 31;
    const int wid  = tid >> 5;
    const int wm = (wid & 1) * 64;    // 2 warps over M (64-row tiles)
    const int wn = (wid >> 1) * 32;   // 8 warps over N (32-col tiles)
    const int bm = blockIdx.y * BM;
    const int bn = blockIdx.x * BN;

    const __nv_bfloat16* Ah = g_Ahi + (size_t)bm * KDIM;
    const __nv_bfloat16* Al = g_Alo + (size_t)bm * KDIM;
    const __nv_bfloat16* Bh = g_Bhi + bn;
    const __nv_bfloat16* Bl = g_Blo + bn;

    float acc[4][4][4];   // [mi][ni(n8)][frag]
#pragma unroll
    for (int i = 0; i < 4; ++i)
#pragma unroll
        for (int j = 0; j < 4; ++j)
#pragma unroll
            for (int k = 0; k < 4; ++k) acc[i][j][k] = 0.0f;

    // ldmatrix base addresses (byte offsets within a stage)
    const int r16 = lane & 15, h4 = lane >> 4;
    const uint32_t a_base = (uint32_t)((wm + r16) * ROWA_B + h4 * 16);
    const uint32_t b_base = (uint32_t)(r16 * ROWB_B + (wn + 8 * h4) * 2);

    auto load_stage = [&](int s, int kt) {
        const uint32_t st = sbase + s * STAGE_B;
        const int k0 = kt * BK;
        // A hi/lo: 128 rows x 8 chunks of 16B (1024 chunks, 2 per thread)
#pragma unroll
        for (int i = 0; i < 2; ++i) {
            const int f = tid + i * NTHREADS;
            const int r = f >> 3, c = f & 7;
            const uint32_t so = (uint32_t)(r * ROWA_B + c * 16);
            const size_t go = (size_t)r * KDIM + k0 + c * 8;
            cp16(st + AHI_OFF + so, Ah + go);
            cp16(st + ALO_OFF + so, Al + go);
        }
        // B hi/lo: 64 rows x 32 chunks of 16B (2048 chunks, 4 per thread)
#pragma unroll
        for (int i = 0; i < 4; ++i) {
            const int f = tid + i * NTHREADS;
            const int r = f >> 5, c = f & 31;
            const uint32_t so = (uint32_t)(r * ROWB_B + c * 16);
            const size_t go = (size_t)(k0 + r) * NDIM + c * 8;
            cp16(st + BHI_OFF + so, Bh + go);
            cp16(st + BLO_OFF + so, Bl + go);
        }
    };

    load_stage(0, 0);
    asm volatile("cp.async.commit_group;\n");

    for (int kt = 0; kt < NK; ++kt) {
        const int s = kt & 1;
        asm volatile("cp.async.wait_group 0;\n");
        __syncthreads();

        if (kt + 1 < NK) {
            load_stage(s ^ 1, kt + 1);
            asm volatile("cp.async.commit_group;\n");
        }

        const uint32_t st = sbase + s * STAGE_B;
#pragma unroll
        for (int k16 = 0; k16 < BK / 16; ++k16) {
            // ---- fragments for this k16: 8 A-LDSM + 4 B-LDSM ----
            uint32_t ah[4][4], al[4][4], bh[2][4], bl[2][4];
#pragma unroll
            for (int mi = 0; mi < 4; ++mi) {
                const uint32_t ad = st + a_base + mi * 16 * ROWA_B + k16 * 32;
                LDSM4(ah[mi], ad + AHI_OFF);
                LDSM4(al[mi], ad + ALO_OFF);
            }
#pragma unroll
            for (int n16 = 0; n16 < 2; ++n16) {
                const uint32_t bd = st + b_base + k16 * 16 * ROWB_B + n16 * 32;
                LDSM4T(bh[n16], bd + BHI_OFF);
                LDSM4T(bl[n16], bd + BLO_OFF);
            }
            // ---- 48 MMAs, pass-major ----
#pragma unroll
            for (int n16 = 0; n16 < 2; ++n16)
#pragma unroll
                for (int mi = 0; mi < 4; ++mi) {
                    MMA(acc[mi][2 * n16 + 0], ah[mi], bh[n16][0], bh[n16][1]);
                    MMA(acc[mi][2 * n16 + 1], ah[mi], bh[n16][2], bh[n16][3]);
                }
#pragma unroll
            for (int n16 = 0; n16 < 2; ++n16)
#pragma unroll
                for (int mi = 0; mi < 4; ++mi) {
                    MMA(acc[mi][2 * n16 + 0], ah[mi], bl[n16][0], bl[n16][1]);
                    MMA(acc[mi][2 * n16 + 1], ah[mi], bl[n16][2], bl[n16][3]);
                }
#pragma unroll
            for (int n16 = 0; n16 < 2; ++n16)
#pragma unroll
                for (int mi = 0; mi < 4; ++mi) {
                    MMA(acc[mi][2 * n16 + 0], al[mi], bh[n16][0], bh[n16][1]);
                    MMA(acc[mi][2 * n16 + 1], al[mi], bh[n16][2], bh[n16][3]);
                }
        }
    }

    // ---------------- epilogue: + (bias+probs), tanh ----------------
    const int g = lane >> 2, tig = lane & 3;
    float2 badd[4];
#pragma unroll
    for (int ni = 0; ni < 4; ++ni)
        badd[ni] = *(const float2*)(g_padd + bn + wn + ni * 8 + 2 * tig);
#pragma unroll
    for (int mi = 0; mi < 4; ++mi) {
        const int row0 = bm + wm + mi * 16 + g;
#pragma unroll
        for (int ni = 0; ni < 4; ++ni) {
            const int col = bn + wn + ni * 8 + 2 * tig;
            float2 v0, v1;
            v0.x = tanhf(acc[mi][ni][0] + badd[ni].x);
            v0.y = tanhf(acc[mi][ni][1] + badd[ni].y);
            v1.x = tanhf(acc[mi][ni][2] + badd[ni].x);
            v1.y = tanhf(acc[mi][ni][3] + badd[ni].y);
            *(float2*)(out + (size_t)row0 * NDIM + col) = v0;
            *(float2*)(out + (size_t)(row0 + 8) * NDIM + col) = v1;
        }
    }
}

// ---------------- launch ----------------
extern "C" void kernel_launch(void* const* d_in, const int* in_sizes, int n_in,
                              void* d_out, int out_size) {
    (void)in_sizes; (void)n_in; (void)out_size;
    const float* x  = (const float*)d_in[0];
    const float* aw = (const float*)d_in[1];
    const float* cw = (const float*)d_in[2];
    const float* cb = (const float*)d_in[3];
    float* out = (float*)d_out;

    static bool attr_done = false;
    if (!attr_done) {
        cudaFuncSetAttribute(gemm_tanh_kernel,
                             cudaFuncAttributeMaxDynamicSharedMemorySize, SMEM_TOTAL);
        attr_done = true;
    }

    __nv_bfloat16 *ahi, *alo, *bhi, *blo;
    cudaGetSymbolAddress((void**)&ahi, g_Ahi);
    cudaGetSymbolAddress((void**)&alo, g_Alo);
    cudaGetSymbolAddress((void**)&bhi, g_Bhi);
    cudaGetSymbolAddress((void**)&blo, g_Blo);

    prep_kernel<<<ABLKS + BBLKS + PRBLKS, 256>>>(x, cw, aw, cb, ahi, alo, bhi, blo);

    dim3 grid(NDIM / BN, BATCH / BM);
    gemm_tanh_kernel<<<grid, NTHREADS, SMEM_TOTAL>>>(out);
}